// round 1
// baseline (speedup 1.0000x reference)
#include <cuda_runtime.h>

#define NROWS 1000000
#define NCOLS 128
#define N_BINS 15

// Scratch (no device allocation allowed): global int histogram + label-dtype flag.
__device__ int g_hist[N_BINS * 2];
__device__ int g_lbl32;  // 1 => labels are int32, 0 => int64

// Kernel 1: zero the histogram and detect label dtype.
// If labels are int64 (little-endian), every odd 32-bit word is a high half == 0
// (values are in [0,128)). If int32, odd words are labels[1],labels[3],... and
// the chance all 64 sampled are zero is (1/128)^64 ~ 0.
__global__ void zero_detect_kernel(const int* __restrict__ labels_raw) {
    int t = threadIdx.x;
    if (t < N_BINS * 2) g_hist[t] = 0;
    if (t == 0) {
        int any = 0;
        #pragma unroll 8
        for (int i = 0; i < 64; i++) any |= labels_raw[2 * i + 1];
        g_lbl32 = (any != 0) ? 1 : 0;
    }
}

// Kernel 2: main pass. One warp per row, grid-stride, prefetch-1.
__global__ __launch_bounds__(512) void conf_acc_kernel(
    const float* __restrict__ logits,
    const void*  __restrict__ labels)
{
    __shared__ int sh[N_BINS * 2];
    if (threadIdx.x < N_BINS * 2) sh[threadIdx.x] = 0;
    __syncthreads();

    const int lane   = threadIdx.x & 31;
    const int warp   = (blockIdx.x * blockDim.x + threadIdx.x) >> 5;
    const int nwarps = (gridDim.x * blockDim.x) >> 5;

    const int        lbl32 = g_lbl32;
    const int*       L32   = (const int*)labels;
    const long long* L64   = (const long long*)labels;

    int r = warp;
    if (r < NROWS) {
        float4 v = ((const float4*)(logits + (size_t)r * NCOLS))[lane];
        for (;;) {
            // Prefetch next row's chunk while we reduce the current one.
            int rn = r + nwarps;
            float4 vn;
            if (rn < NROWS)
                vn = ((const float4*)(logits + (size_t)rn * NCOLS))[lane];

            // ---- per-thread max + first-index over 4 elements ----
            float m  = v.x;
            int  idx = lane * 4;
            if (v.y > m) { m = v.y; idx = lane * 4 + 1; }
            if (v.z > m) { m = v.z; idx = lane * 4 + 2; }
            if (v.w > m) { m = v.w; idx = lane * 4 + 3; }

            // ---- warp xor-butterfly (max, min-index-on-tie) ----
            #pragma unroll
            for (int off = 16; off; off >>= 1) {
                float om = __shfl_xor_sync(0xffffffffu, m,   off);
                int   oi = __shfl_xor_sync(0xffffffffu, idx, off);
                if (om > m || (om == m && oi < idx)) { m = om; idx = oi; }
            }

            // ---- sum of exp(x - m) ----
            float s = __expf(v.x - m) + __expf(v.y - m) +
                      __expf(v.z - m) + __expf(v.w - m);
            #pragma unroll
            for (int off = 16; off; off >>= 1)
                s += __shfl_xor_sync(0xffffffffu, s, off);

            if (lane == 0) {
                float conf = 1.0f / s;                    // max softmax prob
                int b = (int)(conf * 15.0f);              // floor; conf >= 1/128 > 0
                b = b < 0 ? 0 : (b > N_BINS - 1 ? N_BINS - 1 : b);
                int lbl = lbl32 ? L32[r] : (int)L64[r];
                int slot = b * 2 + ((idx == lbl) ? 0 : 1);
                atomicAdd(&sh[slot], 1);
            }

            if (rn >= NROWS) break;
            r = rn;
            v = vn;
        }
    }

    __syncthreads();
    if (threadIdx.x < N_BINS * 2)
        atomicAdd(&g_hist[threadIdx.x], sh[threadIdx.x]);
}

// Kernel 3: convert int counts to float output [N_BINS, 2].
__global__ void finalize_kernel(float* __restrict__ out) {
    int t = threadIdx.x;
    if (t < N_BINS * 2) out[t] = (float)g_hist[t];
}

extern "C" void kernel_launch(void* const* d_in, const int* in_sizes, int n_in,
                              void* d_out, int out_size) {
    const float* logits = (const float*)d_in[0];
    const void*  labels = d_in[1];
    (void)in_sizes; (void)n_in; (void)out_size;

    zero_detect_kernel<<<1, 32>>>((const int*)labels);
    conf_acc_kernel<<<608, 512>>>(logits, labels);
    finalize_kernel<<<1, 32>>>((float*)d_out);
}